// round 14
// baseline (speedup 1.0000x reference)
#include <cuda_runtime.h>

#define NN   116
#define HID  64
#define ENCD 122

// ---- cross-block scratch ----
__device__ float g_dv[NN];
__device__ __align__(16) float g_q[NN * 4];
__device__ float g_S[NN * 5];
__device__ unsigned g_ticket = 0;     // monotone; seq = ticket/NN + 1 per launch
__device__ unsigned g_Sflag[NN];      // >= seq  => S[i] ready

__device__ __forceinline__ int rowoff(int a) { return a * (231 - a) / 2; }
__device__ __forceinline__ int eix(int a, int b) { return rowoff(a) + (b - a - 1); }

// ============================================================================
// K1 (NN+1 x 512): blocks 0..115: node i -> x1 (smem only), dv, q.
// Block 116: bias seed out = bl + b2@Wl. No gE writes (k23 recomputes).
// All global loads batched in phase 0 (one L2 round trip).
// ============================================================================
__global__ void __launch_bounds__(512, 1) k1(
    const float* __restrict__ enc, const float* __restrict__ ea,
    const float* __restrict__ W_enc, const float* __restrict__ b_enc,
    const float* __restrict__ W1, const float* __restrict__ b1,
    const float* __restrict__ p1, const float* __restrict__ pe,
    const float* __restrict__ W2, const float* __restrict__ b2,
    const float* __restrict__ Wl, const float* __restrict__ bl,
    float* __restrict__ out)
{
    const int i = blockIdx.x, t = threadIdx.x;
    const int wq = t >> 5, lane = t & 31;

    if (i >= NN) {                        // bias seed block
        if (t < 128) {
            int o = wq;
            float v = b2[lane] * Wl[lane * 4 + o] + b2[lane + 32] * Wl[(lane + 32) * 4 + o];
            #pragma unroll
            for (int off = 16; off; off >>= 1) v += __shfl_xor_sync(0xffffffffu, v, off);
            if (lane == 0) out[o] = v + bl[o];
        }
        return;
    }

    __shared__ float sd1[120];            // [115..119] = 0
    __shared__ float sMp[8 * 123];
    __shared__ float sM[128];             // [122]=bias lane, [123..127]=0
    __shared__ float sp[512];
    __shared__ float sy[64];
    __shared__ float sx1[64];
    __shared__ float sw[64];

    const int g8 = t >> 6, c2 = t & 63;

    // ---------- Phase 0: batch ALL global loads ----------
    float a5[5];
    const bool eact = t < 115;
    if (eact) {
        int k = t + (t >= i);
        int a = min(i, k), b = max(i, k);
        const float* A = ea + eix(a, b) * 5;
        #pragma unroll
        for (int c = 0; c < 5; c++) a5[c] = A[c];
    }
    float2 rE2[15];
    #pragma unroll
    for (int j = 0; j < 15; ++j) {
        int u = g8 * 15 + j;
        float2 v = make_float2(0.f, 0.f);
        if (c2 < 61 && u < 115) {
            int k = u + (u >= i);
            v = *reinterpret_cast<const float2*>(enc + k * ENCD + 2 * c2);
        }
        rE2[j] = v;
    }
    float rWz[16];
    #pragma unroll
    for (int j = 0; j < 16; ++j) {
        int c = g8 * 16 + j;
        rWz[j] = (c < 122) ? W_enc[c * HID + c2] : ((c == 122) ? b_enc[c2] : 0.f);
    }
    float rW1[8], rW2[8];
    #pragma unroll
    for (int j = 0; j < 8; ++j) {
        rW1[j] = W1[(g8 * 8 + j) * HID + c2];
        rW2[j] = W2[(g8 * 8 + j) * HID + c2];
    }
    float rb1 = (t < 64) ? b1[t] : 0.f;
    float rpe0 = 0.f, rpe1 = 0.f;
    if (t < 32) { rpe0 = pe[t]; rpe1 = pe[t + 32]; }
    float rWl0 = 0.f, rWl1 = 0.f;
    if (t < 128) { rWl0 = Wl[lane * 4 + wq]; rWl1 = Wl[(lane + 32) * 4 + wq]; }

    // ---------- d1 ----------
    if (eact) {
        sd1[t] = a5[0] * __ldg(&p1[0]) + a5[1] * __ldg(&p1[1]) + a5[2] * __ldg(&p1[2])
               + a5[3] * __ldg(&p1[3]) + a5[4] * __ldg(&p1[4]);
    }
    if (t >= 115 && t < 120) sd1[t] = 0.f;
    __syncthreads();

    // ---------- M stage ----------
    if (c2 < 61) {
        float s0 = 0.f, s1 = 0.f;
        #pragma unroll
        for (int j = 0; j < 15; ++j) {
            float d = sd1[g8 * 15 + j];
            s0 += rE2[j].x * d;
            s1 += rE2[j].y * d;
        }
        sMp[g8 * 123 + 2 * c2]     = s0;
        sMp[g8 * 123 + 2 * c2 + 1] = s1;
    } else if (c2 == 61) {
        float s = 0.f;
        #pragma unroll
        for (int j = 0; j < 15; ++j) {
            int u = g8 * 15 + j;
            if (u < 115) s += sd1[u];
        }
        sMp[g8 * 123 + 122] = s;
    }
    __syncthreads();
    if (t < 123) {
        float s = 0.f;
        #pragma unroll
        for (int q = 0; q < 8; ++q) s += sMp[q * 123 + t];
        sM[t] = s;
    }
    if (t >= 123 && t < 128) sM[t] = 0.f;
    __syncthreads();

    // ---------- y = M @ [W_enc; b_enc; 0] ----------
    {
        float s = 0.f;
        #pragma unroll
        for (int j = 0; j < 16; ++j) s += sM[g8 * 16 + j] * rWz[j];
        sp[g8 * 64 + c2] = s;
    }
    __syncthreads();
    if (t < HID) {
        float s = sp[t];
        #pragma unroll
        for (int q = 1; q < 8; ++q) s += sp[q * 64 + t];
        sy[t] = s;
    }
    __syncthreads();

    // ---------- x1 = relu(b1 + y @ W1) ----------
    {
        float s = 0.f;
        #pragma unroll
        for (int j = 0; j < 8; ++j) s += sy[g8 * 8 + j] * rW1[j];
        sp[g8 * 64 + c2] = s;
    }
    __syncthreads();
    if (t < HID) {
        float s = sp[t];
        #pragma unroll
        for (int q = 1; q < 8; ++q) s += sp[q * 64 + t];
        sx1[t] = fmaxf(rb1 + s, 0.f);
    }
    __syncthreads();

    // ---------- dv (warp 0) concurrent with w partials (all) ----------
    if (t < 32) {
        float s = sx1[t] * rpe0 + sx1[t + 32] * rpe1;
        #pragma unroll
        for (int off = 16; off; off >>= 1) s += __shfl_xor_sync(0xffffffffu, s, off);
        if (t == 0) g_dv[i] = s;
    }
    {
        float s = 0.f;
        #pragma unroll
        for (int j = 0; j < 8; ++j) s += sx1[g8 * 8 + j] * rW2[j];
        sp[g8 * 64 + c2] = s;
    }
    __syncthreads();
    if (t < HID) {
        float s = sp[t];
        #pragma unroll
        for (int q = 1; q < 8; ++q) s += sp[q * 64 + t];
        sw[t] = s;
    }
    __syncthreads();
    if (t < 128) {                        // q[o] = sw . Wl[:,o]
        float qv = sw[lane] * rWl0 + sw[lane + 32] * rWl1;
        #pragma unroll
        for (int off = 16; off; off >>= 1) qv += __shfl_xor_sync(0xffffffffu, qv, off);
        if (lane == 0) g_q[i * 4 + wq] = qv;
    }
}

// ============================================================================
// K23 (PDL, NN x 128): PREAMBLE (overlaps k1): recompute gg from ea inputs,
// grab seq ticket, load be/p2/We. Then griddepsync -> dv -> S -> flag ring ->
// D -> atomic out.
// ============================================================================
__global__ void __launch_bounds__(128, 1) k23(
    const float* __restrict__ ea, const float* __restrict__ We,
    const float* __restrict__ be, const float* __restrict__ p2,
    float* __restrict__ out)
{
    __shared__ float sdv[NN];
    __shared__ float sS[NN * 5];
    __shared__ float wsum[4 * 5];
    __shared__ float wred[4];
    __shared__ unsigned s_seq;
    const int i = blockIdx.x, t = threadIdx.x;
    const int wq = t >> 5, lane = t & 31;

    // ---- PREAMBLE: input-only work, overlaps k1 execution ----
    if (t == 0) s_seq = atomicAdd(&g_ticket, 1u) / NN + 1u;
    float gg[5] = {0.f, 0.f, 0.f, 0.f, 0.f};
    int kn = 0;
    const bool eact = t < 115;
    if (eact) {
        kn = t + (t >= i);
        int a = min(i, kn), b = max(i, kn);
        const float* A = ea + eix(a, b) * 5;
        float r5[5];
        #pragma unroll
        for (int c = 0; c < 5; c++) r5[c] = fmaxf(A[c], 0.f);
        #pragma unroll
        for (int cc = 0; cc < 5; cc++) {
            gg[cc] = r5[0] * __ldg(&We[cc]) + r5[1] * __ldg(&We[5 + cc])
                   + r5[2] * __ldg(&We[10 + cc]) + r5[3] * __ldg(&We[15 + cc])
                   + r5[4] * __ldg(&We[20 + cc]);
        }
    }
    float rbe[5], rp2[5];
    #pragma unroll
    for (int c = 0; c < 5; c++) { rbe[c] = __ldg(&be[c]); rp2[c] = __ldg(&p2[c]); }

    cudaGridDependencySynchronize();      // k1 done: dv, q, out-seed valid

    // batch post-sync loads: dv + q
    if (t < NN) sdv[t] = g_dv[t];
    float rq = (t < 4) ? g_q[i * 4 + t] : 0.f;
    __syncthreads();
    const unsigned seq = s_seq;

    // ---- S[i] (gg in registers) ----
    float inv = 0.f;
    {
        float s5[5] = {0.f, 0.f, 0.f, 0.f, 0.f};
        if (eact) {
            inv = 1.f / (fmaxf(fmaxf(sdv[i], sdv[kn]), 0.f) + 1e-10f);
            #pragma unroll
            for (int c = 0; c < 5; c++) s5[c] = gg[c] * inv;
        }
        #pragma unroll
        for (int c = 0; c < 5; c++) {
            float v = s5[c];
            #pragma unroll
            for (int off = 16; off; off >>= 1) v += __shfl_xor_sync(0xffffffffu, v, off);
            if (lane == 0) wsum[wq * 5 + c] = v;
        }
    }
    __syncthreads();
    if (t < 5) g_S[i * 5 + t] = wsum[t] + wsum[5 + t] + wsum[10 + t] + wsum[15 + t];
    __syncthreads();
    if (t == 0) {
        __threadfence();                  // release S before flag
        g_Sflag[i] = seq;
    }

    // ---- wait all S (single-writer epoch flags; all 116 blocks resident) ----
    if (t < NN) {
        while (*(volatile unsigned*)&g_Sflag[t] < seq) {}
    }
    __threadfence();                      // acquire
    __syncthreads();
    if (t < NN) {
        #pragma unroll
        for (int c = 0; c < 5; c++) sS[t * 5 + c] = g_S[t * 5 + c];
    }
    __syncthreads();

    // ---- D[i] + output ----
    float partv = 0.f;
    if (eact) {
        float dvi = sdv[i], dvk = sdv[kn];
        #pragma unroll
        for (int c = 0; c < 5; c++) {
            float hh = gg[c] * inv;
            float v = dvi * (sS[i * 5 + c] - hh) + dvk * (sS[kn * 5 + c] - hh) + rbe[c];
            partv += fmaxf(v, 0.f) * rp2[c];
        }
    }
    #pragma unroll
    for (int off = 16; off; off >>= 1) partv += __shfl_xor_sync(0xffffffffu, partv, off);
    if (lane == 0) wred[wq] = partv;
    __syncthreads();
    if (t < 4) {
        float D = wred[0] + wred[1] + wred[2] + wred[3];
        atomicAdd(&out[t], D * rq * (1.0f / (float)NN));
    }
}

extern "C" void kernel_launch(void* const* d_in, const int* in_sizes, int n_in,
                              void* d_out, int out_size) {
    const float* enc   = (const float*)d_in[0];
    const float* ea    = (const float*)d_in[1];
    // d_in[2] = edge_index (triu order, closed-form reproduced) — unused
    const float* W_enc = (const float*)d_in[3];
    const float* b_enc = (const float*)d_in[4];
    const float* W1    = (const float*)d_in[5];
    const float* b1    = (const float*)d_in[6];
    const float* p1    = (const float*)d_in[7];
    const float* We    = (const float*)d_in[8];
    const float* be    = (const float*)d_in[9];
    const float* pe    = (const float*)d_in[10];
    const float* W2    = (const float*)d_in[11];
    const float* b2    = (const float*)d_in[12];
    const float* p2    = (const float*)d_in[13];
    const float* Wl    = (const float*)d_in[14];
    const float* bl    = (const float*)d_in[15];
    float* out = (float*)d_out;

    cudaLaunchAttribute attr[1];
    attr[0].id = cudaLaunchAttributeProgrammaticStreamSerialization;
    attr[0].val.programmaticStreamSerializationAllowed = 1;

    k1<<<NN + 1, 512>>>(enc, ea, W_enc, b_enc, W1, b1, p1, pe, W2, b2, Wl, bl, out);
    {
        cudaLaunchConfig_t cfg = {};
        cfg.gridDim = dim3(NN); cfg.blockDim = dim3(128);
        cfg.attrs = attr; cfg.numAttrs = 1; cfg.stream = 0;
        cudaLaunchKernelEx(&cfg, k23, ea, We, be, p2, out);
    }
}

// round 15
// speedup vs baseline: 1.1478x; 1.1478x over previous
#include <cuda_runtime.h>

#define NN   116
#define NE   6670
#define HID  64
#define ENCD 122

// ---- device scratch ----
__device__ float g_gE[NE * 5];
__device__ float g_dv[NN];
__device__ __align__(16) float g_x1[NN * HID];
__device__ __align__(16) float g_Wc[HID * 4];    // W2 @ Wl
__device__ float g_S[NN * 5];

__device__ __forceinline__ int rowoff(int a) { return a * (231 - a) / 2; }
__device__ __forceinline__ int eix(int a, int b) { return rowoff(a) + (b - a - 1); }

// ============================================================================
// K1 (116 x 512): block per node i. All global loads batched up front with
// vectorized, warp-coalesced access (float2), then pure smem/FMA stages.
// ============================================================================
__global__ void __launch_bounds__(512, 1) k1(
    const float* __restrict__ enc, const float* __restrict__ ea,
    const float* __restrict__ W_enc, const float* __restrict__ b_enc,
    const float* __restrict__ W1, const float* __restrict__ b1,
    const float* __restrict__ p1, const float* __restrict__ We,
    const float* __restrict__ pe)
{
    __shared__ float sd1[120];            // [115..119] = 0
    __shared__ float sMp[8 * 123];
    __shared__ float sM[128];             // [122]=bias lane, [123..127]=0
    __shared__ float sp[1024];
    __shared__ float sy[64];
    __shared__ float sx1[64];

    const int i = blockIdx.x, t = threadIdx.x;
    const int g8 = t >> 6, c2 = t & 63;   // M stage: row-chunk g8, col-pair c2
    const int gr = t >> 5, mp = t & 31;   // y/x1 stage: c-chunk gr, m-pair mp

    // ---------- Phase 0: batch-issue ALL global loads (vectorized) ----------
    float a5[5];
    int eg = 0, ka = 0;
    const bool eact = t < 115;
    if (eact) {
        int k = t + (t >= i);
        ka = min(i, k);
        int kb = max(i, k);
        eg = eix(ka, kb);
        const float* A = ea + eg * 5;
        #pragma unroll
        for (int c = 0; c < 5; c++) a5[c] = A[c];
    }
    // enc: col pair (2c2, 2c2+1), 15-row slice g8 — warp-contiguous float2
    float2 rE2[15];
    #pragma unroll
    for (int j = 0; j < 15; ++j) {
        int u = g8 * 15 + j;
        float2 v = make_float2(0.f, 0.f);
        if (c2 < 61 && u < 115) {
            int k = u + (u >= i);
            v = *reinterpret_cast<const float2*>(enc + k * ENCD + 2 * c2);
        }
        rE2[j] = v;
    }
    // y-stage weights: c = gr*8+j (128 >= 124 rows of [W_enc; b_enc; 0]), m-pair mp
    float2 rWz2[8];
    #pragma unroll
    for (int j = 0; j < 8; ++j) {
        int c = gr * 8 + j;
        float2 v = make_float2(0.f, 0.f);
        if (c < 122)      v = *reinterpret_cast<const float2*>(W_enc + c * HID + 2 * mp);
        else if (c == 122) v = *reinterpret_cast<const float2*>(b_enc + 2 * mp);
        rWz2[j] = v;
    }
    // x1-stage weights: c = gr*4+j (64 rows of W1), m-pair mp
    float2 rW12[4];
    #pragma unroll
    for (int j = 0; j < 4; ++j) {
        int c = gr * 4 + j;
        rW12[j] = *reinterpret_cast<const float2*>(W1 + c * HID + 2 * mp);
    }
    float rb1 = (t < 64) ? b1[t] : 0.f;
    float rpe0 = 0.f, rpe1 = 0.f;
    if (t < 32) { rpe0 = pe[t]; rpe1 = pe[t + 32]; }

    // ---------- d1 + gE ----------
    if (eact) {
        float r5[5];
        #pragma unroll
        for (int c = 0; c < 5; c++) r5[c] = fmaxf(a5[c], 0.f);
        sd1[t] = a5[0] * __ldg(&p1[0]) + a5[1] * __ldg(&p1[1]) + a5[2] * __ldg(&p1[2])
               + a5[3] * __ldg(&p1[3]) + a5[4] * __ldg(&p1[4]);
        if (ka == i) {                    // row-owner writes each edge's gE once
            #pragma unroll
            for (int cc = 0; cc < 5; cc++) {
                float gg = r5[0] * __ldg(&We[cc]) + r5[1] * __ldg(&We[5 + cc])
                         + r5[2] * __ldg(&We[10 + cc]) + r5[3] * __ldg(&We[15 + cc])
                         + r5[4] * __ldg(&We[20 + cc]);
                g_gE[eg * 5 + cc] = gg;
            }
        }
    }
    if (t >= 115 && t < 120) sd1[t] = 0.f;
    __syncthreads();

    // ---------- M stage (float2 col pairs, 8 row-chunks) ----------
    if (c2 < 61) {
        float s0 = 0.f, s1 = 0.f;
        #pragma unroll
        for (int j = 0; j < 15; ++j) {
            float d = sd1[g8 * 15 + j];
            s0 += rE2[j].x * d;
            s1 += rE2[j].y * d;
        }
        sMp[g8 * 123 + 2 * c2]     = s0;
        sMp[g8 * 123 + 2 * c2 + 1] = s1;
    } else if (c2 == 61) {                // bias lane: plain sum of d1
        float s = 0.f;
        #pragma unroll
        for (int j = 0; j < 15; ++j) {
            int u = g8 * 15 + j;
            if (u < 115) s += sd1[u];
        }
        sMp[g8 * 123 + 122] = s;
    }
    __syncthreads();
    if (t < 123) {
        float s = 0.f;
        #pragma unroll
        for (int q = 0; q < 8; ++q) s += sMp[q * 123 + t];
        sM[t] = s;
    }
    if (t >= 123 && t < 128) sM[t] = 0.f;
    __syncthreads();

    // ---------- y = M @ [W_enc; b_enc; 0] : 16 c-chunks x m-pairs ----------
    {
        float s0 = 0.f, s1 = 0.f;
        #pragma unroll
        for (int j = 0; j < 8; ++j) {
            float mv = sM[gr * 8 + j];
            s0 += mv * rWz2[j].x;
            s1 += mv * rWz2[j].y;
        }
        sp[gr * 64 + 2 * mp]     = s0;
        sp[gr * 64 + 2 * mp + 1] = s1;
    }
    __syncthreads();
    if (t < HID) {
        float s = 0.f;
        #pragma unroll
        for (int q = 0; q < 16; ++q) s += sp[q * 64 + t];
        sy[t] = s;
    }
    __syncthreads();

    // ---------- x1 = relu(b1 + y @ W1) : 16 c-chunks x m-pairs ----------
    {
        float s0 = 0.f, s1 = 0.f;
        #pragma unroll
        for (int j = 0; j < 4; ++j) {
            float yv = sy[gr * 4 + j];
            s0 += yv * rW12[j].x;
            s1 += yv * rW12[j].y;
        }
        sp[gr * 64 + 2 * mp]     = s0;
        sp[gr * 64 + 2 * mp + 1] = s1;
    }
    __syncthreads();
    if (t < HID) {
        float s = 0.f;
        #pragma unroll
        for (int q = 0; q < 16; ++q) s += sp[q * 64 + t];
        float x = fmaxf(rb1 + s, 0.f);
        sx1[t] = x;
        g_x1[i * HID + t] = x;
    }
    __syncthreads();

    // ---------- dv = x1 . pe ----------
    if (t < 32) {
        float s = sx1[t] * rpe0 + sx1[t + 32] * rpe1;
        #pragma unroll
        for (int off = 16; off; off >>= 1) s += __shfl_xor_sync(0xffffffffu, s, off);
        if (t == 0) g_dv[i] = s;
    }
}

// ============================================================================
// K2 (PDL): blocks 0..115: S[i,c]; blocks 116,117: Wc = W2@Wl + bias seed.
// ============================================================================
__global__ void __launch_bounds__(128, 1) k2(
    const float* __restrict__ W2, const float* __restrict__ b2,
    const float* __restrict__ Wl, const float* __restrict__ bl,
    float* __restrict__ out)
{
    const int i = blockIdx.x, t = threadIdx.x;

    if (i >= NN) {
        int idx = (i - NN) * 128 + t;    // 0..255
        int k = idx >> 2, o = idx & 3;
        float s = 0.f;
        #pragma unroll
        for (int mm = 0; mm < HID; mm++) s += W2[k * HID + mm] * Wl[mm * 4 + o];
        g_Wc[idx] = s;
        if (i == NN && t < 4) {
            float v = bl[t];
            #pragma unroll
            for (int mm = 0; mm < HID; mm++) v += b2[mm] * Wl[mm * 4 + t];
            out[t] = v;
        }
        return;
    }

    cudaGridDependencySynchronize();

    __shared__ float sdv[NN];
    __shared__ float wsum[4 * 5];
    const int wq = t >> 5, lane = t & 31;

    float a5[5] = {0.f, 0.f, 0.f, 0.f, 0.f};
    int kn = 0;
    if (t < 115) {
        kn = t + (t >= i);
        int a = min(i, kn), b = max(i, kn);
        int e = eix(a, b);
        #pragma unroll
        for (int c = 0; c < 5; c++) a5[c] = g_gE[e * 5 + c];
    }
    if (t < NN) sdv[t] = g_dv[t];
    __syncthreads();

    float s5[5] = {0.f, 0.f, 0.f, 0.f, 0.f};
    if (t < 115) {
        float inv = 1.f / (fmaxf(fmaxf(sdv[i], sdv[kn]), 0.f) + 1e-10f);
        #pragma unroll
        for (int c = 0; c < 5; c++) s5[c] = a5[c] * inv;
    }
    #pragma unroll
    for (int c = 0; c < 5; c++) {
        #pragma unroll
        for (int off = 16; off; off >>= 1) s5[c] += __shfl_xor_sync(0xffffffffu, s5[c], off);
        if (lane == 0) wsum[wq * 5 + c] = s5[c];
    }
    __syncthreads();
    if (t < 5) g_S[i * 5 + t] = wsum[t] + wsum[5 + t] + wsum[10 + t] + wsum[15 + t];
}

// ============================================================================
// K3 (PDL): D[i]; q[i] = x1[i]@Wc inline; out[o] += D * q[o] / NN.
// ============================================================================
__global__ void __launch_bounds__(128, 1) k3(
    const float* __restrict__ be, const float* __restrict__ p2,
    float* __restrict__ out)
{
    cudaGridDependencySynchronize();

    __shared__ float sdv[NN];
    __shared__ float sS[NN * 5];
    __shared__ float sx1r[HID];
    __shared__ __align__(16) float sWc[HID * 4];
    __shared__ float wred[4];
    const int i = blockIdx.x, t = threadIdx.x;
    const int wq = t >> 5, lane = t & 31;

    float a5[5] = {0.f, 0.f, 0.f, 0.f, 0.f};
    int kn = 0;
    if (t < 115) {
        kn = t + (t >= i);
        int a = min(i, kn), b = max(i, kn);
        int e = eix(a, b);
        #pragma unroll
        for (int c = 0; c < 5; c++) a5[c] = g_gE[e * 5 + c];
    }
    if (t < NN) sdv[t] = g_dv[t];
    #pragma unroll
    for (int r = 0; r < 5; ++r) {
        int u = t + r * 128;
        if (u < NN * 5) sS[u] = g_S[u];
    }
    if (t < HID) sx1r[t] = g_x1[i * HID + t];
    if (t < 64) reinterpret_cast<float4*>(sWc)[t] = reinterpret_cast<const float4*>(g_Wc)[t];
    float rbe[5], rp2[5];
    #pragma unroll
    for (int c = 0; c < 5; c++) { rbe[c] = __ldg(&be[c]); rp2[c] = __ldg(&p2[c]); }
    __syncthreads();

    float dvi = sdv[i];
    float partv = 0.f;
    if (t < 115) {
        float dvk = sdv[kn];
        float inv = 1.f / (fmaxf(fmaxf(dvi, dvk), 0.f) + 1e-10f);
        #pragma unroll
        for (int c = 0; c < 5; c++) {
            float hh = a5[c] * inv;
            float v = dvi * (sS[i * 5 + c] - hh) + dvk * (sS[kn * 5 + c] - hh) + rbe[c];
            partv += fmaxf(v, 0.f) * rp2[c];
        }
    }
    #pragma unroll
    for (int off = 16; off; off >>= 1) partv += __shfl_xor_sync(0xffffffffu, partv, off);
    if (lane == 0) wred[wq] = partv;
    __syncthreads();

    {
        int o = wq;
        float qv = sx1r[lane] * sWc[lane * 4 + o] + sx1r[lane + 32] * sWc[(lane + 32) * 4 + o];
        #pragma unroll
        for (int off = 16; off; off >>= 1) qv += __shfl_xor_sync(0xffffffffu, qv, off);
        if (lane == 0) {
            float D = wred[0] + wred[1] + wred[2] + wred[3];
            atomicAdd(&out[o], D * qv * (1.0f / (float)NN));
        }
    }
}

extern "C" void kernel_launch(void* const* d_in, const int* in_sizes, int n_in,
                              void* d_out, int out_size) {
    const float* enc   = (const float*)d_in[0];
    const float* ea    = (const float*)d_in[1];
    // d_in[2] = edge_index (triu order, closed-form reproduced) — unused
    const float* W_enc = (const float*)d_in[3];
    const float* b_enc = (const float*)d_in[4];
    const float* W1    = (const float*)d_in[5];
    const float* b1    = (const float*)d_in[6];
    const float* p1    = (const float*)d_in[7];
    const float* We    = (const float*)d_in[8];
    const float* be    = (const float*)d_in[9];
    const float* pe    = (const float*)d_in[10];
    const float* W2    = (const float*)d_in[11];
    const float* b2    = (const float*)d_in[12];
    const float* p2    = (const float*)d_in[13];
    const float* Wl    = (const float*)d_in[14];
    const float* bl    = (const float*)d_in[15];
    float* out = (float*)d_out;

    cudaLaunchAttribute attr[1];
    attr[0].id = cudaLaunchAttributeProgrammaticStreamSerialization;
    attr[0].val.programmaticStreamSerializationAllowed = 1;

    k1<<<NN, 512>>>(enc, ea, W_enc, b_enc, W1, b1, p1, We, pe);
    {
        cudaLaunchConfig_t cfg = {};
        cfg.gridDim = dim3(NN + 2); cfg.blockDim = dim3(128);
        cfg.attrs = attr; cfg.numAttrs = 1; cfg.stream = 0;
        cudaLaunchKernelEx(&cfg, k2, W2, b2, Wl, bl, out);
    }
    {
        cudaLaunchConfig_t cfg = {};
        cfg.gridDim = dim3(NN); cfg.blockDim = dim3(128);
        cfg.attrs = attr; cfg.numAttrs = 1; cfg.stream = 0;
        cudaLaunchKernelEx(&cfg, k3, be, p2, out);
    }
}